// round 2
// baseline (speedup 1.0000x reference)
#include <cuda_runtime.h>

#define BATCH 2
#define SEQ   2048
#define DM    1024
#define NH    16
#define DH    64
#define MTOT  (BATCH * SEQ)   // 4096

#define QK_LD 68   // 64 + 4 pad, keeps float4 alignment, conflict-free
#define PS_LD 65

// scratch (allocation-free rule: __device__ globals)
__device__ float g_Q[BATCH * NH * SEQ * DH];
__device__ float g_K[BATCH * NH * SEQ * DH];
__device__ float g_V[BATCH * NH * SEQ * DH];
__device__ float g_H[MTOT * DM];

// ---------------------------------------------------------------------------
// GEMM core: C[64x64] tile = A[m0:m0+64, :] * B[:, n0:n0+64], K=1024
// 256 threads, each 4x4. BK=16.
// ---------------------------------------------------------------------------
__device__ __forceinline__ void gemm_core(const float* __restrict__ A,
                                          const float* __restrict__ B,
                                          int m0, int n0, int K,
                                          int ldA, int ldB,
                                          float acc[4][4]) {
    __shared__ float As[16][64];
    __shared__ float Bs[16][64];

    const int tid   = threadIdx.x;
    const int tx    = tid & 15;
    const int ty    = tid >> 4;
    const int arow  = tid >> 2;          // 0..63
    const int acol4 = (tid & 3) << 2;    // 0,4,8,12
    const int brow  = tid >> 4;          // 0..15
    const int bcol4 = (tid & 15) << 2;   // 0..60

    for (int kt = 0; kt < K; kt += 16) {
        __syncthreads();
        float4 av = *(const float4*)(A + (size_t)(m0 + arow) * ldA + kt + acol4);
        As[acol4 + 0][arow] = av.x;
        As[acol4 + 1][arow] = av.y;
        As[acol4 + 2][arow] = av.z;
        As[acol4 + 3][arow] = av.w;
        float4 bv = *(const float4*)(B + (size_t)(kt + brow) * ldB + n0 + bcol4);
        *(float4*)&Bs[brow][bcol4] = bv;
        __syncthreads();

        #pragma unroll
        for (int kk = 0; kk < 16; kk++) {
            float4 a = *(const float4*)&As[kk][ty << 2];
            float4 b = *(const float4*)&Bs[kk][tx << 2];
            acc[0][0] = fmaf(a.x, b.x, acc[0][0]);
            acc[0][1] = fmaf(a.x, b.y, acc[0][1]);
            acc[0][2] = fmaf(a.x, b.z, acc[0][2]);
            acc[0][3] = fmaf(a.x, b.w, acc[0][3]);
            acc[1][0] = fmaf(a.y, b.x, acc[1][0]);
            acc[1][1] = fmaf(a.y, b.y, acc[1][1]);
            acc[1][2] = fmaf(a.y, b.z, acc[1][2]);
            acc[1][3] = fmaf(a.y, b.w, acc[1][3]);
            acc[2][0] = fmaf(a.z, b.x, acc[2][0]);
            acc[2][1] = fmaf(a.z, b.y, acc[2][1]);
            acc[2][2] = fmaf(a.z, b.z, acc[2][2]);
            acc[2][3] = fmaf(a.z, b.w, acc[2][3]);
            acc[3][0] = fmaf(a.w, b.x, acc[3][0]);
            acc[3][1] = fmaf(a.w, b.y, acc[3][1]);
            acc[3][2] = fmaf(a.w, b.z, acc[3][2]);
            acc[3][3] = fmaf(a.w, b.w, acc[3][3]);
        }
    }
}

// ---------------------------------------------------------------------------
// QKV projections: y = x @ W + b, scattered to [B, H, S, Dh]
// ---------------------------------------------------------------------------
__global__ __launch_bounds__(256)
void qkv_gemm_kernel(const float* __restrict__ x,
                     const float* __restrict__ Wq, const float* __restrict__ bq,
                     const float* __restrict__ Wk, const float* __restrict__ bk,
                     const float* __restrict__ Wv, const float* __restrict__ bv) {
    const int m0 = blockIdx.y << 6;
    const int n0 = blockIdx.x << 6;
    const int which = blockIdx.z;
    const float* W    = (which == 0) ? Wq : (which == 1) ? Wk : Wv;
    const float* bias = (which == 0) ? bq : (which == 1) ? bk : bv;
    float* out        = (which == 0) ? g_Q : (which == 1) ? g_K : g_V;

    float acc[4][4] = {};
    gemm_core(x, W, m0, n0, DM, DM, DM, acc);

    const int tx = threadIdx.x & 15;
    const int ty = threadIdx.x >> 4;
    #pragma unroll
    for (int i = 0; i < 4; i++) {
        const int m = m0 + (ty << 2) + i;
        const int b = m >> 11;          // m / SEQ
        const int s = m & (SEQ - 1);
        #pragma unroll
        for (int j = 0; j < 4; j++) {
            const int n = n0 + (tx << 2) + j;
            const int h = n >> 6;
            const int d = n & 63;
            out[((size_t)((b * NH + h) * SEQ + s) << 6) + d] = acc[i][j] + bias[n];
        }
    }
}

// ---------------------------------------------------------------------------
// Output projection: out = g_H @ Wo + bo
// ---------------------------------------------------------------------------
__global__ __launch_bounds__(256)
void out_gemm_kernel(const float* __restrict__ Wo, const float* __restrict__ bo,
                     float* __restrict__ out) {
    const int m0 = blockIdx.y << 6;
    const int n0 = blockIdx.x << 6;

    float acc[4][4] = {};
    gemm_core(g_H, Wo, m0, n0, DM, DM, DM, acc);

    const int tx = threadIdx.x & 15;
    const int ty = threadIdx.x >> 4;
    #pragma unroll
    for (int i = 0; i < 4; i++) {
        const int m = m0 + (ty << 2) + i;
        #pragma unroll
        for (int j = 0; j < 4; j++) {
            const int n = n0 + (tx << 2) + j;
            out[(size_t)m * DM + n] = acc[i][j] + bo[n];
        }
    }
}

// ---------------------------------------------------------------------------
// Causal flash attention: one (q-tile 64, batch*head) per block. 256 threads.
// Thread (row, sub): row = warp*8 + lane/4, sub = lane%4.
// Scores: cols c = sub + 4j (interleaved). O: dims d = sub*16 + i (contiguous).
// ---------------------------------------------------------------------------
__global__ __launch_bounds__(256)
void attn_kernel() {
    extern __shared__ float sm[];
    float* Qs = sm;                       // 64 * QK_LD
    float* Ks = Qs + 64 * QK_LD;
    float* Vs = Ks + 64 * QK_LD;
    float* Ps = Vs + 64 * QK_LD;          // 64 * PS_LD

    const int qt = (gridDim.x - 1) - blockIdx.x;  // heavy tiles first
    const int bh = blockIdx.y;
    const int b  = bh / NH;
    const int h  = bh % NH;

    const float* Qg = g_Q + (size_t)(bh * SEQ + (qt << 6)) * DH;
    const float* Kg = g_K + (size_t)bh * SEQ * DH;
    const float* Vg = g_V + (size_t)bh * SEQ * DH;

    const int tid  = threadIdx.x;
    const int lane = tid & 31;
    const int warp = tid >> 5;
    const int row  = (warp << 3) + (lane >> 2);
    const int sub  = lane & 3;

    // load Q tile [64 x 64]
    {
        const int r = tid >> 2;
        const int c = (tid & 3) << 4;
        #pragma unroll
        for (int q = 0; q < 16; q += 4)
            *(float4*)&Qs[r * QK_LD + c + q] = *(const float4*)(Qg + r * DH + c + q);
    }

    float O[16];
    #pragma unroll
    for (int i = 0; i < 16; i++) O[i] = 0.f;
    float mrun = -1e30f, lrun = 0.f;
    const float scale = 0.125f;           // 1/sqrt(64)
    const int qglob = (qt << 6) + row;

    for (int kt = 0; kt <= qt; kt++) {
        __syncthreads();
        // load K, V tiles [64 x 64]
        {
            const int r = tid >> 2;
            const int c = (tid & 3) << 4;
            const float* kp = Kg + (size_t)((kt << 6) + r) * DH + c;
            const float* vp = Vg + (size_t)((kt << 6) + r) * DH + c;
            #pragma unroll
            for (int q = 0; q < 16; q += 4) {
                *(float4*)&Ks[r * QK_LD + c + q] = *(const float4*)(kp + q);
                *(float4*)&Vs[r * QK_LD + c + q] = *(const float4*)(vp + q);
            }
        }
        __syncthreads();

        // scores s[j] = Q[row] . K[sub + 4j]
        float s[16];
        #pragma unroll
        for (int j = 0; j < 16; j++) s[j] = 0.f;
        #pragma unroll 4
        for (int d4 = 0; d4 < 16; d4++) {
            float4 qv = *(const float4*)&Qs[row * QK_LD + (d4 << 2)];
            #pragma unroll
            for (int j = 0; j < 16; j++) {
                float4 kv = *(const float4*)&Ks[(sub + (j << 2)) * QK_LD + (d4 << 2)];
                s[j] = fmaf(qv.x, kv.x, s[j]);
                s[j] = fmaf(qv.y, kv.y, s[j]);
                s[j] = fmaf(qv.z, kv.z, s[j]);
                s[j] = fmaf(qv.w, kv.w, s[j]);
            }
        }

        // scale + causal mask
        #pragma unroll
        for (int j = 0; j < 16; j++) {
            const int kglob = (kt << 6) + sub + (j << 2);
            s[j] = (kglob <= qglob) ? s[j] * scale : -1e30f;
        }

        // row max across 16 regs + 4 lanes
        float mloc = s[0];
        #pragma unroll
        for (int j = 1; j < 16; j++) mloc = fmaxf(mloc, s[j]);
        mloc = fmaxf(mloc, __shfl_xor_sync(0xffffffffu, mloc, 1));
        mloc = fmaxf(mloc, __shfl_xor_sync(0xffffffffu, mloc, 2));
        const float mnew  = fmaxf(mrun, mloc);
        const float alpha = __expf(mrun - mnew);

        float lloc = 0.f;
        #pragma unroll
        for (int j = 0; j < 16; j++) {
            s[j] = __expf(s[j] - mnew);
            lloc += s[j];
        }
        lloc += __shfl_xor_sync(0xffffffffu, lloc, 1);
        lloc += __shfl_xor_sync(0xffffffffu, lloc, 2);
        lrun = lrun * alpha + lloc;
        mrun = mnew;

        #pragma unroll
        for (int i = 0; i < 16; i++) O[i] *= alpha;

        // stage P to smem (own row only -> warp-local)
        #pragma unroll
        for (int j = 0; j < 16; j++)
            Ps[row * PS_LD + sub + (j << 2)] = s[j];
        __syncwarp();

        // O[d] += sum_k P[row][k] * V[k][d], d = sub*16 + i
        #pragma unroll 4
        for (int k = 0; k < 64; k++) {
            const float p = Ps[row * PS_LD + k];
            const float4* v4 = (const float4*)&Vs[k * QK_LD + (sub << 4)];
            float4 va = v4[0], vb = v4[1], vc = v4[2], vd = v4[3];
            O[0]  = fmaf(p, va.x, O[0]);
            O[1]  = fmaf(p, va.y, O[1]);
            O[2]  = fmaf(p, va.z, O[2]);
            O[3]  = fmaf(p, va.w, O[3]);
            O[4]  = fmaf(p, vb.x, O[4]);
            O[5]  = fmaf(p, vb.y, O[5]);
            O[6]  = fmaf(p, vb.z, O[6]);
            O[7]  = fmaf(p, vb.w, O[7]);
            O[8]  = fmaf(p, vc.x, O[8]);
            O[9]  = fmaf(p, vc.y, O[9]);
            O[10] = fmaf(p, vc.z, O[10]);
            O[11] = fmaf(p, vc.w, O[11]);
            O[12] = fmaf(p, vd.x, O[12]);
            O[13] = fmaf(p, vd.y, O[13]);
            O[14] = fmaf(p, vd.z, O[14]);
            O[15] = fmaf(p, vd.w, O[15]);
        }
    }

    // epilogue: normalize and write to g_H [B, S, D]
    const float inv = 1.0f / lrun;
    float* out = g_H + (size_t)(b * SEQ + (qt << 6) + row) * DM + h * DH + (sub << 4);
    #pragma unroll
    for (int i = 0; i < 4; i++) {
        float4 o = make_float4(O[4 * i + 0] * inv, O[4 * i + 1] * inv,
                               O[4 * i + 2] * inv, O[4 * i + 3] * inv);
        *(float4*)(out + 4 * i) = o;
    }
}

// ---------------------------------------------------------------------------
extern "C" void kernel_launch(void* const* d_in, const int* in_sizes, int n_in,
                              void* d_out, int out_size) {
    const float* x  = (const float*)d_in[0];
    const float* Wq = (const float*)d_in[1];
    const float* bq = (const float*)d_in[2];
    const float* Wk = (const float*)d_in[3];
    const float* bk = (const float*)d_in[4];
    const float* Wv = (const float*)d_in[5];
    const float* bv = (const float*)d_in[6];
    const float* Wo = (const float*)d_in[7];
    const float* bo = (const float*)d_in[8];
    float* out = (float*)d_out;

    // 1. QKV projections
    dim3 gq(DM / 64, MTOT / 64, 3);
    qkv_gemm_kernel<<<gq, 256>>>(x, Wq, bq, Wk, bk, Wv, bv);

    // 2. causal flash attention
    const size_t smem = (size_t)(3 * 64 * QK_LD + 64 * PS_LD) * sizeof(float);
    cudaFuncSetAttribute(attn_kernel, cudaFuncAttributeMaxDynamicSharedMemorySize,
                         (int)smem);
    attn_kernel<<<dim3(SEQ / 64, BATCH * NH), 256, smem>>>();

    // 3. output projection
    out_gemm_kernel<<<dim3(DM / 64, MTOT / 64), 256>>>(Wo, bo, out);
}

// round 3
// speedup vs baseline: 2.0663x; 2.0663x over previous
#include <cuda_runtime.h>

#define BATCH 2
#define SEQ   2048
#define DM    1024
#define NH    16
#define DH    64
#define MTOT  (BATCH * SEQ)   // 4096

#define BM 128
#define BN 128
#define BK 8

#define AT_LD 68   // 64 + 4 pad; keeps 16B alignment (68 floats = 272B = 17*16B)

// scratch (allocation-free rule: __device__ globals)
__device__ float g_Q[BATCH * NH * SEQ * DH];
__device__ float g_K[BATCH * NH * SEQ * DH];
__device__ float g_V[BATCH * NH * SEQ * DH];
__device__ float g_H[MTOT * DM];

// ---------------------------------------------------------------------------
// SGEMM core: 128x128 tile, 8x8 per thread, BK=8, double-buffered smem,
// register prefetch of next global tile. K fixed = DM = 1024.
// ---------------------------------------------------------------------------
__device__ __forceinline__ void sgemm_tile(const float* __restrict__ A,
                                           const float* __restrict__ B,
                                           int m0, int n0, int lda, int ldb,
                                           float acc[8][8]) {
    __shared__ float As[2 * BK * BM];
    __shared__ float Bs[2 * BK * BN];

    const int tid  = threadIdx.x;
    const int arow = tid >> 1;          // 0..127
    const int ak   = (tid & 1) << 2;    // 0 or 4
    const int bk   = tid >> 5;          // 0..7
    const int bcol = (tid & 31) << 2;   // 0..124
    const int ty   = tid >> 4;          // 0..15
    const int tx   = tid & 15;          // 0..15

    const float* Ap = A + (size_t)(m0 + arow) * lda + ak;
    const float* Bp = B + (size_t)bk * ldb + n0 + bcol;

    // prologue: tile 0
    {
        float4 av = *(const float4*)Ap;
        float4 bv = *(const float4*)Bp;
        As[(ak + 0) * BM + arow] = av.x;
        As[(ak + 1) * BM + arow] = av.y;
        As[(ak + 2) * BM + arow] = av.z;
        As[(ak + 3) * BM + arow] = av.w;
        *(float4*)&Bs[bk * BN + bcol] = bv;
    }
    __syncthreads();

    int buf = 0;
    for (int kt = BK; kt <= DM; kt += BK) {
        float4 av2, bv2;
        const bool more = (kt < DM);
        if (more) {
            av2 = *(const float4*)(Ap + kt);
            bv2 = *(const float4*)(Bp + (size_t)kt * ldb);
        }
        const float* as = As + buf * (BK * BM);
        const float* bs = Bs + buf * (BK * BN);
        #pragma unroll
        for (int k = 0; k < BK; k++) {
            float a[8], b[8];
            *(float4*)&a[0] = *(const float4*)&as[k * BM + (ty << 2)];
            *(float4*)&a[4] = *(const float4*)&as[k * BM + 64 + (ty << 2)];
            *(float4*)&b[0] = *(const float4*)&bs[k * BN + (tx << 2)];
            *(float4*)&b[4] = *(const float4*)&bs[k * BN + 64 + (tx << 2)];
            #pragma unroll
            for (int i = 0; i < 8; i++)
                #pragma unroll
                for (int j = 0; j < 8; j++)
                    acc[i][j] = fmaf(a[i], b[j], acc[i][j]);
        }
        if (more) {
            buf ^= 1;
            float* asn = As + buf * (BK * BM);
            float* bsn = Bs + buf * (BK * BN);
            asn[(ak + 0) * BM + arow] = av2.x;
            asn[(ak + 1) * BM + arow] = av2.y;
            asn[(ak + 2) * BM + arow] = av2.z;
            asn[(ak + 3) * BM + arow] = av2.w;
            *(float4*)&bsn[bk * BN + bcol] = bv2;
            __syncthreads();
        }
    }
}

// ---------------------------------------------------------------------------
// QKV projections: y = x @ W + b, scattered to [B, H, S, Dh]
// ---------------------------------------------------------------------------
__global__ __launch_bounds__(256, 2)
void qkv_gemm_kernel(const float* __restrict__ x,
                     const float* __restrict__ Wq, const float* __restrict__ bq,
                     const float* __restrict__ Wk, const float* __restrict__ bk,
                     const float* __restrict__ Wv, const float* __restrict__ bv) {
    const int m0 = blockIdx.y << 7;
    const int n0 = blockIdx.x << 7;
    const int which = blockIdx.z;
    const float* W    = (which == 0) ? Wq : (which == 1) ? Wk : Wv;
    const float* bias = (which == 0) ? bq : (which == 1) ? bk : bv;
    float* out        = (which == 0) ? g_Q : (which == 1) ? g_K : g_V;

    float acc[8][8] = {};
    sgemm_tile(x, W, m0, n0, DM, DM, acc);

    const int ty = threadIdx.x >> 4;
    const int tx = threadIdx.x & 15;
    #pragma unroll
    for (int ih = 0; ih < 2; ih++) {
        #pragma unroll
        for (int i = 0; i < 4; i++) {
            const int m = m0 + ih * 64 + (ty << 2) + i;
            const int b = m >> 11;
            const int s = m & (SEQ - 1);
            #pragma unroll
            for (int jh = 0; jh < 2; jh++) {
                const int n = n0 + jh * 64 + (tx << 2);
                const int h = n >> 6;
                const int d = n & 63;
                float4 o = make_float4(acc[ih * 4 + i][jh * 4 + 0] + bias[n + 0],
                                       acc[ih * 4 + i][jh * 4 + 1] + bias[n + 1],
                                       acc[ih * 4 + i][jh * 4 + 2] + bias[n + 2],
                                       acc[ih * 4 + i][jh * 4 + 3] + bias[n + 3]);
                *(float4*)&out[((size_t)((b * NH + h) * SEQ + s) << 6) + d] = o;
            }
        }
    }
}

// ---------------------------------------------------------------------------
// Output projection: out = g_H @ Wo + bo
// ---------------------------------------------------------------------------
__global__ __launch_bounds__(256, 2)
void out_gemm_kernel(const float* __restrict__ Wo, const float* __restrict__ bo,
                     float* __restrict__ out) {
    const int m0 = blockIdx.y << 7;
    const int n0 = blockIdx.x << 7;

    float acc[8][8] = {};
    sgemm_tile(g_H, Wo, m0, n0, DM, DM, acc);

    const int ty = threadIdx.x >> 4;
    const int tx = threadIdx.x & 15;
    #pragma unroll
    for (int ih = 0; ih < 2; ih++) {
        #pragma unroll
        for (int i = 0; i < 4; i++) {
            const int m = m0 + ih * 64 + (ty << 2) + i;
            #pragma unroll
            for (int jh = 0; jh < 2; jh++) {
                const int n = n0 + jh * 64 + (tx << 2);
                float4 o = make_float4(acc[ih * 4 + i][jh * 4 + 0] + bo[n + 0],
                                       acc[ih * 4 + i][jh * 4 + 1] + bo[n + 1],
                                       acc[ih * 4 + i][jh * 4 + 2] + bo[n + 2],
                                       acc[ih * 4 + i][jh * 4 + 3] + bo[n + 3]);
                *(float4*)&out[(size_t)m * DM + n] = o;
            }
        }
    }
}

// ---------------------------------------------------------------------------
// Causal flash attention, 2D register blocking.
// Block: 256 threads, q-tile 64, key-tile 64. Thread (ty=tid>>4, tx=tid&15)
// owns score tile rows {4ty+i} x cols {4tx+j} and O tile rows {4ty+i} x
// dh-dims {4tx+j}. Q,K staged transposed (Qt[d][r], Kt[d][c]); V natural.
// ---------------------------------------------------------------------------
__global__ __launch_bounds__(256)
void attn_kernel() {
    extern __shared__ float smf[];
    float* Qt = smf;                   // [64][AT_LD]  Qt[d][r]
    float* Kt = Qt + 64 * AT_LD;       // [64][AT_LD]  Kt[d][c]
    float* Vs = Kt + 64 * AT_LD;       // [64][AT_LD]  Vs[k][d]
    float* Ps = Vs + 64 * AT_LD;       // [64][AT_LD]  Ps[r][k]

    const int qt = (gridDim.x - 1) - blockIdx.x;  // heavy tiles first
    const int bh = blockIdx.y;
    const int b  = bh / NH;
    const int h  = bh % NH;

    const float* Qg = g_Q + (size_t)(bh * SEQ + (qt << 6)) * DH;
    const float* Kg = g_K + (size_t)bh * SEQ * DH;
    const float* Vg = g_V + (size_t)bh * SEQ * DH;

    const int tid = threadIdx.x;
    const int ty  = tid >> 4;
    const int tx  = tid & 15;
    const int lr  = tid >> 2;          // loader row 0..63
    const int ld0 = (tid & 3) << 4;    // loader dim start

    // load Q tile transposed: Qt[d][r]
    {
        const float* qp = Qg + lr * DH + ld0;
        #pragma unroll
        for (int q = 0; q < 16; q += 4) {
            float4 v = *(const float4*)(qp + q);
            Qt[(ld0 + q + 0) * AT_LD + lr] = v.x;
            Qt[(ld0 + q + 1) * AT_LD + lr] = v.y;
            Qt[(ld0 + q + 2) * AT_LD + lr] = v.z;
            Qt[(ld0 + q + 3) * AT_LD + lr] = v.w;
        }
    }

    float O[4][4];
    float mrun[4], lrun[4];
    #pragma unroll
    for (int i = 0; i < 4; i++) {
        mrun[i] = -1e30f;
        lrun[i] = 0.f;
        #pragma unroll
        for (int j = 0; j < 4; j++) O[i][j] = 0.f;
    }
    const float scale = 0.125f;        // 1/sqrt(64)
    const int qrow0 = (qt << 6) + (ty << 2);

    for (int kt = 0; kt <= qt; kt++) {
        __syncthreads();
        // load K transposed + V natural
        {
            const float* kp = Kg + (size_t)((kt << 6) + lr) * DH + ld0;
            const float* vp = Vg + (size_t)((kt << 6) + lr) * DH + ld0;
            #pragma unroll
            for (int q = 0; q < 16; q += 4) {
                float4 kv = *(const float4*)(kp + q);
                Kt[(ld0 + q + 0) * AT_LD + lr] = kv.x;
                Kt[(ld0 + q + 1) * AT_LD + lr] = kv.y;
                Kt[(ld0 + q + 2) * AT_LD + lr] = kv.z;
                Kt[(ld0 + q + 3) * AT_LD + lr] = kv.w;
                *(float4*)&Vs[lr * AT_LD + ld0 + q] = *(const float4*)(vp + q);
            }
        }
        __syncthreads();

        // scores s[i][j] = Q[4ty+i] . K[4tx+j]
        float s[4][4] = {};
        #pragma unroll 8
        for (int d = 0; d < 64; d++) {
            float4 q4 = *(const float4*)&Qt[d * AT_LD + (ty << 2)];
            float4 k4 = *(const float4*)&Kt[d * AT_LD + (tx << 2)];
            s[0][0] = fmaf(q4.x, k4.x, s[0][0]);
            s[0][1] = fmaf(q4.x, k4.y, s[0][1]);
            s[0][2] = fmaf(q4.x, k4.z, s[0][2]);
            s[0][3] = fmaf(q4.x, k4.w, s[0][3]);
            s[1][0] = fmaf(q4.y, k4.x, s[1][0]);
            s[1][1] = fmaf(q4.y, k4.y, s[1][1]);
            s[1][2] = fmaf(q4.y, k4.z, s[1][2]);
            s[1][3] = fmaf(q4.y, k4.w, s[1][3]);
            s[2][0] = fmaf(q4.z, k4.x, s[2][0]);
            s[2][1] = fmaf(q4.z, k4.y, s[2][1]);
            s[2][2] = fmaf(q4.z, k4.z, s[2][2]);
            s[2][3] = fmaf(q4.z, k4.w, s[2][3]);
            s[3][0] = fmaf(q4.w, k4.x, s[3][0]);
            s[3][1] = fmaf(q4.w, k4.y, s[3][1]);
            s[3][2] = fmaf(q4.w, k4.z, s[3][2]);
            s[3][3] = fmaf(q4.w, k4.w, s[3][3]);
        }

        // scale (+ causal mask only on the diagonal tile)
        if (kt == qt) {
            #pragma unroll
            for (int i = 0; i < 4; i++) {
                const int qg = qrow0 + i;
                #pragma unroll
                for (int j = 0; j < 4; j++) {
                    const int kg = (kt << 6) + (tx << 2) + j;
                    s[i][j] = (kg <= qg) ? s[i][j] * scale : -1e30f;
                }
            }
        } else {
            #pragma unroll
            for (int i = 0; i < 4; i++)
                #pragma unroll
                for (int j = 0; j < 4; j++) s[i][j] *= scale;
        }

        // online softmax per row (reduce across 16 tx lanes)
        #pragma unroll
        for (int i = 0; i < 4; i++) {
            float m = fmaxf(fmaxf(s[i][0], s[i][1]), fmaxf(s[i][2], s[i][3]));
            m = fmaxf(m, __shfl_xor_sync(0xffffffffu, m, 1));
            m = fmaxf(m, __shfl_xor_sync(0xffffffffu, m, 2));
            m = fmaxf(m, __shfl_xor_sync(0xffffffffu, m, 4));
            m = fmaxf(m, __shfl_xor_sync(0xffffffffu, m, 8));
            const float mnew  = fmaxf(mrun[i], m);
            const float alpha = __expf(mrun[i] - mnew);
            float l = 0.f;
            #pragma unroll
            for (int j = 0; j < 4; j++) {
                s[i][j] = __expf(s[i][j] - mnew);
                l += s[i][j];
            }
            l += __shfl_xor_sync(0xffffffffu, l, 1);
            l += __shfl_xor_sync(0xffffffffu, l, 2);
            l += __shfl_xor_sync(0xffffffffu, l, 4);
            l += __shfl_xor_sync(0xffffffffu, l, 8);
            lrun[i] = lrun[i] * alpha + l;
            mrun[i] = mnew;
            #pragma unroll
            for (int j = 0; j < 4; j++) O[i][j] *= alpha;
            // stage P row (warp-local: rows 4ty+i produced by same warp)
            *(float4*)&Ps[((ty << 2) + i) * AT_LD + (tx << 2)] =
                make_float4(s[i][0], s[i][1], s[i][2], s[i][3]);
        }
        __syncwarp();

        // O[i][j] += sum_k P[4ty+i][k] * V[k][4tx+j]
        #pragma unroll 4
        for (int k4 = 0; k4 < 64; k4 += 4) {
            float4 p0 = *(const float4*)&Ps[((ty << 2) + 0) * AT_LD + k4];
            float4 p1 = *(const float4*)&Ps[((ty << 2) + 1) * AT_LD + k4];
            float4 p2 = *(const float4*)&Ps[((ty << 2) + 2) * AT_LD + k4];
            float4 p3 = *(const float4*)&Ps[((ty << 2) + 3) * AT_LD + k4];
            #pragma unroll
            for (int t = 0; t < 4; t++) {
                float4 v = *(const float4*)&Vs[(k4 + t) * AT_LD + (tx << 2)];
                const float pa = (t == 0) ? p0.x : (t == 1) ? p0.y : (t == 2) ? p0.z : p0.w;
                const float pb = (t == 0) ? p1.x : (t == 1) ? p1.y : (t == 2) ? p1.z : p1.w;
                const float pc = (t == 0) ? p2.x : (t == 1) ? p2.y : (t == 2) ? p2.z : p2.w;
                const float pd = (t == 0) ? p3.x : (t == 1) ? p3.y : (t == 2) ? p3.z : p3.w;
                O[0][0] = fmaf(pa, v.x, O[0][0]);
                O[0][1] = fmaf(pa, v.y, O[0][1]);
                O[0][2] = fmaf(pa, v.z, O[0][2]);
                O[0][3] = fmaf(pa, v.w, O[0][3]);
                O[1][0] = fmaf(pb, v.x, O[1][0]);
                O[1][1] = fmaf(pb, v.y, O[1][1]);
                O[1][2] = fmaf(pb, v.z, O[1][2]);
                O[1][3] = fmaf(pb, v.w, O[1][3]);
                O[2][0] = fmaf(pc, v.x, O[2][0]);
                O[2][1] = fmaf(pc, v.y, O[2][1]);
                O[2][2] = fmaf(pc, v.z, O[2][2]);
                O[2][3] = fmaf(pc, v.w, O[2][3]);
                O[3][0] = fmaf(pd, v.x, O[3][0]);
                O[3][1] = fmaf(pd, v.y, O[3][1]);
                O[3][2] = fmaf(pd, v.z, O[3][2]);
                O[3][3] = fmaf(pd, v.w, O[3][3]);
            }
        }
    }

    // epilogue: normalize, write to g_H [B, S, D]
    #pragma unroll
    for (int i = 0; i < 4; i++) {
        const float inv = 1.0f / lrun[i];
        float* outp = g_H + (size_t)(b * SEQ + (qt << 6) + (ty << 2) + i) * DM
                          + h * DH + (tx << 2);
        *(float4*)outp = make_float4(O[i][0] * inv, O[i][1] * inv,
                                     O[i][2] * inv, O[i][3] * inv);
    }
}

// ---------------------------------------------------------------------------
extern "C" void kernel_launch(void* const* d_in, const int* in_sizes, int n_in,
                              void* d_out, int out_size) {
    const float* x  = (const float*)d_in[0];
    const float* Wq = (const float*)d_in[1];
    const float* bq = (const float*)d_in[2];
    const float* Wk = (const float*)d_in[3];
    const float* bk = (const float*)d_in[4];
    const float* Wv = (const float*)d_in[5];
    const float* bv = (const float*)d_in[6];
    const float* Wo = (const float*)d_in[7];
    const float* bo = (const float*)d_in[8];
    float* out = (float*)d_out;

    // 1. QKV projections
    dim3 gq(DM / BN, MTOT / BM, 3);
    qkv_gemm_kernel<<<gq, 256>>>(x, Wq, bq, Wk, bk, Wv, bv);

    // 2. causal flash attention
    const size_t smem = (size_t)(4 * 64 * AT_LD) * sizeof(float);
    cudaFuncSetAttribute(attn_kernel, cudaFuncAttributeMaxDynamicSharedMemorySize,
                         (int)smem);
    attn_kernel<<<dim3(SEQ / 64, BATCH * NH), 256, smem>>>();

    // 3. output projection
    out_gemm_kernel<<<dim3(DM / BN, MTOT / BM), 256>>>(Wo, bo, out);
}